// round 17
// baseline (speedup 1.0000x reference)
#include <cuda_runtime.h>
#include <cuda_fp16.h>
#include <cstdint>

// ---------------- problem constants ----------------
#define N_ROWS 131072
#define F_IN   256
#define N_SRC  32
#define F_OUT  64
#define W_COLS (N_SRC * F_OUT)   // 2048

#define BM 128
#define BK 32
#define CHUNKS (F_IN / BK)       // 8
#define NTHREADS 256
#define CAP 8192
#define TILES_PER_SRC 40          // 5120 rows capacity; count = 4096 +- 63
#define VTILES (N_SRC * TILES_PER_SRC)  // 1280 virtual tiles
#define GRID_GEMM 444             // 148 SMs x 3 CTAs, persistent

// stage layout:
//   A (double-buffered): 128 rows x 80B pitch (32 fp16 + pad) per chunk
//   B (resident across tiles of same source): 64 rows x 528B pitch
#define SB   80
#define SBB  528
#define A_BYTES (BM * SB)              // 10240
#define B_BYTES (F_OUT * SBB)          // 33792
#define OFF_B   (2 * A_BYTES)          // 20480
#define SM_PERM 0
#define SM_STAGE 640
#define SM_TOTAL (SM_STAGE + OFF_B + B_BYTES)  // 54912

// ---------------- device scratch (zero-init is the valid initial state) ----------------
__device__ int g_cursor[N_SRC * 32];   // counts from 0; reset by gemm last-finisher
__device__ int g_done;                 // persistent-block completion counter
__device__ int g_perm[N_SRC * CAP];
__device__ __half g_Wh[N_SRC * F_OUT * F_IN];   // [src][n][k], fp16

// ---------------- pass 0 (fused): scatter + prepW ----------------
__global__ void k_prep(const int* __restrict__ src, const float* __restrict__ W) {
    __shared__ float tile[64][65];
    const int tid = threadIdx.x;
    if (blockIdx.x < 128) {
        int i0 = (blockIdx.x * 256 + tid) * 4;
        int4 s4 = *(const int4*)(src + i0);
        int sv[4] = { s4.x, s4.y, s4.z, s4.w };
        int lane = tid & 31;
        #pragma unroll
        for (int j = 0; j < 4; j++) {
            int s = sv[j];
            unsigned m = __match_any_sync(0xffffffffu, s);
            int leader = __ffs(m) - 1;
            int rank = __popc(m & ((1u << lane) - 1));
            int base = 0;
            if (lane == leader) base = atomicAdd(&g_cursor[s * 32], __popc(m));
            base = __shfl_sync(0xffffffffu, base, leader);
            g_perm[s * CAP + base + rank] = i0 + j;
        }
    } else {
        const int bid = blockIdx.x - 128;
        const int s = bid >> 2;
        const int c = bid & 3;
        #pragma unroll
        for (int q = 0; q < 16; q++) {
            int idx = q * 256 + tid;
            int kk = idx >> 6, n = idx & 63;
            tile[kk][n] = W[(size_t)(c * 64 + kk) * W_COLS + s * F_OUT + n];
        }
        __syncthreads();
        #pragma unroll
        for (int q = 0; q < 16; q++) {
            int idx = q * 256 + tid;
            int n = idx >> 6, kk = idx & 63;
            size_t o = (size_t)(s * F_OUT + n) * F_IN + c * 64 + kk;
            g_Wh[o] = __float2half_rn(tile[kk][n]);
        }
    }
}

// ---------------- wrappers ----------------
__device__ __forceinline__ void mma_f16(float* c, const uint32_t* a,
                                        uint32_t b0, uint32_t b1) {
    asm volatile(
        "mma.sync.aligned.m16n8k16.row.col.f32.f16.f16.f32 "
        "{%0,%1,%2,%3}, {%4,%5,%6,%7}, {%8,%9}, {%0,%1,%2,%3};"
        : "+f"(c[0]), "+f"(c[1]), "+f"(c[2]), "+f"(c[3])
        : "r"(a[0]), "r"(a[1]), "r"(a[2]), "r"(a[3]), "r"(b0), "r"(b1));
}
__device__ __forceinline__ void ldm_x4(uint32_t* r, uint32_t addr) {
    asm volatile("ldmatrix.sync.aligned.m8n8.x4.shared.b16 {%0,%1,%2,%3}, [%4];"
        : "=r"(r[0]), "=r"(r[1]), "=r"(r[2]), "=r"(r[3]) : "r"(addr));
}
__device__ __forceinline__ void cpa16(uint32_t dst, const void* src, int srcsz) {
    asm volatile("cp.async.ca.shared.global [%0], [%1], 16, %2;"
        :: "r"(dst), "l"(src), "r"(srcsz) : "memory");
}
__device__ __forceinline__ void cpa_commit() {
    asm volatile("cp.async.commit_group;" ::: "memory");
}

// ---------------- pass 1: persistent HMMA GEMM ----------------
// 444 blocks x 256 threads / 8 warps; warp tile = 32 rows x 32 cols.
// Each block owns contiguous virtual tiles [vlo, vhi) in source-major order:
// B stays resident in smem while the source is unchanged.
__global__ void __launch_bounds__(NTHREADS, 3)
k_gemm(const float* __restrict__ x, const float* __restrict__ b,
       float* __restrict__ out) {
    extern __shared__ char smem[];
    const int tid = threadIdx.x;
    const int wid = tid >> 5;
    const int lid = tid & 31;
    const int g4 = lid >> 2;
    const int q4 = lid & 3;
    const int mw = wid >> 1;
    const int nw = wid & 1;

    // A staging lane map (STS.128 bank-conflict-free): a phase of 8 lanes
    // covers 8 distinct rows at one 32B half -> spans r*5 mod 8, all distinct.
    const int arow  = wid * 16 + (lid & 7) + ((lid >> 4) & 1) * 8;
    const int ahalf = (lid >> 3) & 1;

    int* sperm = (int*)(smem + SM_PERM);
    const uint32_t smb = (uint32_t)__cvta_generic_to_shared(smem);
    const uint32_t stage0 = smb + SM_STAGE;

    const int vlo = (int)((long)blockIdx.x * VTILES / GRID_GEMM);
    const int vhi = (int)((long)(blockIdx.x + 1) * VTILES / GRID_GEMM);
    int cur_src = -1;

    const uint32_t offA = ((lid & 7) + ((lid >> 3) & 1) * 8) * SB + ((lid >> 4) & 1) * 16;
    const uint32_t offB = ((lid & 7) + ((lid >> 4) & 1) * 8) * SBB + ((lid >> 3) & 1) * 16;

    #pragma unroll 1
    for (int v = vlo; v < vhi; v++) {
        const int src   = v / TILES_PER_SRC;
        const int local = v - src * TILES_PER_SRC;
        const int count = g_cursor[src * 32];   // uniform broadcast load
        if (local * BM >= count) continue;

        __syncthreads();   // prev tile's epilogue (sperm reads) done
        if (tid < BM) sperm[tid] = g_perm[src * CAP + local * BM + tid];

        const bool stageB = (src != cur_src);
        cur_src = src;
        if (stageB) {
            const char* wsrc = (const char*)(g_Wh + (size_t)src * F_OUT * F_IN);
            #pragma unroll
            for (int q = 0; q < 8; q++) {
                int i = q * NTHREADS + tid;
                int n = i >> 5, g = i & 31;
                cpa16(stage0 + OFF_B + n * SBB + g * 16,
                      wsrc + (n * F_IN + g * 8) * 2, 16);
            }
            cpa_commit();
        }
        __syncthreads();   // sperm visible

        const bool avalid = (local * BM + arow) < count;
        const int aprow = avalid ? sperm[arow] : 0;
        const float* aptr = x + (size_t)aprow * F_IN + ahalf * 16;

        auto ldgA = [&](int c, float4* pf) {
            const float4* g = (const float4*)(aptr + c * BK);
            #pragma unroll
            for (int i = 0; i < 4; i++) pf[i] = __ldg(g + i);
        };
        auto stsA = [&](const float4* pf, int buf) {
            uint32_t h[8];
            #pragma unroll
            for (int i = 0; i < 4; i++) {
                __half2 p0 = __floats2half2_rn(pf[i].x, pf[i].y);
                __half2 p1 = __floats2half2_rn(pf[i].z, pf[i].w);
                h[i * 2 + 0] = *(uint32_t*)&p0;
                h[i * 2 + 1] = *(uint32_t*)&p1;
            }
            char* dst = smem + SM_STAGE + buf * A_BYTES + arow * SB + ahalf * 32;
            *(uint4*)(dst)      = make_uint4(h[0], h[1], h[2], h[3]);
            *(uint4*)(dst + 16) = make_uint4(h[4], h[5], h[6], h[7]);
        };

        float4 pf[4];
        ldgA(0, pf);
        stsA(pf, 0);
        if (stageB) asm volatile("cp.async.wait_group 0;" ::: "memory");
        __syncthreads();

        float acc[2][4][4];
        #pragma unroll
        for (int mb = 0; mb < 2; mb++)
            #pragma unroll
            for (int nb = 0; nb < 4; nb++)
                #pragma unroll
                for (int j = 0; j < 4; j++) acc[mb][nb][j] = 0.0f;

        const uint32_t bB = stage0 + OFF_B + offB + (uint32_t)(nw * 32) * SBB;

        #pragma unroll 1
        for (int c = 0; c < CHUNKS; c++) {
            const int buf = c & 1;
            if (c + 1 < CHUNKS) ldgA(c + 1, pf);

            const uint32_t aA = stage0 + buf * A_BYTES + offA + (uint32_t)(mw * 32) * SB;
            const uint32_t kof = (uint32_t)(c * 64);

            #pragma unroll
            for (int ks = 0; ks < 2; ks++) {
                uint32_t a[2][4];
                #pragma unroll
                for (int mb = 0; mb < 2; mb++)
                    ldm_x4(a[mb], aA + (uint32_t)(mb * 16) * SB + ks * 32);
                #pragma unroll
                for (int p = 0; p < 2; p++) {
                    uint32_t bw[4];
                    ldm_x4(bw, bB + (uint32_t)(p * 16) * SBB + kof + ks * 32);
                    #pragma unroll
                    for (int mb = 0; mb < 2; mb++) {
                        mma_f16(acc[mb][p * 2 + 0], a[mb], bw[0], bw[1]);
                        mma_f16(acc[mb][p * 2 + 1], a[mb], bw[2], bw[3]);
                    }
                }
            }

            if (c + 1 < CHUNKS) stsA(pf, buf ^ 1);
            __syncthreads();
        }

        // epilogue: bias + scattered store (count-based validity)
        #pragma unroll
        for (int p = 0; p < 2; p++) {
            #pragma unroll
            for (int nh = 0; nh < 2; nh++) {
                int col = nw * 32 + p * 16 + nh * 8 + q4 * 2;
                float2 bv = *(const float2*)(b + src * F_OUT + col);
                #pragma unroll
                for (int mb = 0; mb < 2; mb++) {
                    #pragma unroll
                    for (int rh = 0; rh < 2; rh++) {
                        int r = mw * 32 + mb * 16 + g4 + rh * 8;
                        if (local * BM + r < count) {
                            int prow = sperm[r];
                            float2 o;
                            o.x = acc[mb][p * 2 + nh][rh * 2 + 0] + bv.x;
                            o.y = acc[mb][p * 2 + nh][rh * 2 + 1] + bv.y;
                            *(float2*)(out + (size_t)prow * F_OUT + col) = o;
                        }
                    }
                }
            }
        }
    }

    // last-finisher resets cursors for the next graph replay
    if (tid == 0) {
        int old = atomicAdd(&g_done, 1);
        if (old == GRID_GEMM - 1) {
            #pragma unroll
            for (int s = 0; s < N_SRC; s++) g_cursor[s * 32] = 0;
            g_done = 0;
            __threadfence();
        }
    }
}

// ---------------- launch ----------------
extern "C" void kernel_launch(void* const* d_in, const int* in_sizes, int n_in,
                              void* d_out, int out_size) {
    const float* x   = (const float*)d_in[0];
    const int*   src = (const int*)d_in[1];
    const float* W   = (const float*)d_in[2];
    const float* b   = (const float*)d_in[3];
    float* out = (float*)d_out;

    cudaFuncSetAttribute(k_gemm, cudaFuncAttributeMaxDynamicSharedMemorySize, SM_TOTAL);

    k_prep<<<256, 256>>>(src, W);
    k_gemm<<<GRID_GEMM, NTHREADS, SM_TOTAL>>>(x, b, out);
}